// round 15
// baseline (speedup 1.0000x reference)
#include <cuda_runtime.h>
#include <cuda_fp16.h>
#include <cstdint>

// ---------------------------------------------------------------------------
// Problem dims (fixed): B=4, L=4096, H=1024, F=4096
// ---------------------------------------------------------------------------
constexpr int TT = 16384;   // tokens
constexpr int HD = 1024;
constexpr int FD = 4096;

constexpr int BM = 128, BN = 256, BK = 32;
constexpr int STAGES = 4;                        // power of 2 (mask indexing)
constexpr int A_TILE_HALFS = BM * BK;            // 4096 (8 KB)
constexpr int B_TILE_HALFS = BN * BK;            // 8192 (16 KB)
constexpr int A_TILE_BYTES = A_TILE_HALFS * 2;
constexpr int B_TILE_BYTES = B_TILE_HALFS * 2;
constexpr int SMEM_BYTES   = 128 * 260 * 4;      // 133120 (>= pipe 96 KB)

constexpr int NTHREADS = 512;                    // 16 warps: 2 M x 8 N

// ---------------------------------------------------------------------------
// Scratch (allocation-free rule: module-scope device globals), fp16 permuted
// ---------------------------------------------------------------------------
__device__ __align__(1024) __half g_Xr [(size_t)TT * HD];   //  32 MB
__device__ __align__(1024) __half g_W1T[(size_t)FD * HD];   //   8 MB
__device__ __align__(1024) __half g_W2T[(size_t)HD * FD];   //   8 MB
__device__ __align__(1024) __half g_H  [(size_t)TT * FD];   // 134 MB

// ---------------------------------------------------------------------------
// Helpers
// ---------------------------------------------------------------------------
__device__ __forceinline__ uint32_t smem_u32(const void* p) {
    uint32_t a;
    asm("{ .reg .u64 t; cvta.to.shared.u64 t, %1; cvt.u32.u64 %0, t; }" : "=r"(a) : "l"(p));
    return a;
}

__device__ __forceinline__ void cp_async16(uint32_t smem_addr, const void* gptr) {
    asm volatile("cp.async.cg.shared.global [%0], [%1], 16;"
                 :: "r"(smem_addr), "l"(gptr) : "memory");
}
#define CP_COMMIT() asm volatile("cp.async.commit_group;" ::: "memory")
#define CP_WAIT(n)  asm volatile("cp.async.wait_group %0;" :: "n"(n) : "memory")

__device__ __forceinline__ void lds128(uint32_t* r, uint32_t addr) {
    asm volatile("ld.shared.v4.b32 {%0,%1,%2,%3}, [%4];"
                 : "=r"(r[0]), "=r"(r[1]), "=r"(r[2]), "=r"(r[3]) : "r"(addr));
}
__device__ __forceinline__ void lds64(uint32_t* r, uint32_t addr) {
    asm volatile("ld.shared.v2.b32 {%0,%1}, [%2];"
                 : "=r"(r[0]), "=r"(r[1]) : "r"(addr));
}

// fp16 MMA: D(f32) += A(f16) * B(f16), 16x8x16
__device__ __forceinline__ void mma_f16(float* c, const uint32_t* a, const uint32_t* b) {
    asm volatile(
        "mma.sync.aligned.m16n8k16.row.col.f32.f16.f16.f32 "
        "{%0,%1,%2,%3}, {%4,%5,%6,%7}, {%8,%9}, {%0,%1,%2,%3};"
        : "+f"(c[0]), "+f"(c[1]), "+f"(c[2]), "+f"(c[3])
        : "r"(a[0]), "r"(a[1]), "r"(a[2]), "r"(a[3]), "r"(b[0]), "r"(b[1]));
}

// ---------------------------------------------------------------------------
// fp16 fragment layouts:
//  A tile [128 r][32 k]: [ks:2][g:8][lane:32][8 fp16] — 4 A-regs = 16B chunk
//  B tile [256 n][32 k]: [ks:2][ng:32][lane:32][4 fp16] — 2 B-regs = 8B chunk
// ---------------------------------------------------------------------------
__device__ __forceinline__ int off_A16(int r, int kk) {
    int ks = kk >> 4, kr = kk & 15;
    int hk = kr >> 3, c2 = (kr & 7) >> 1, lo = kr & 1;
    int g = r >> 4, rr = r & 15, hm = rr >> 3, lh = rr & 7;
    return (((ks * 8 + g) * 32) + lh * 4 + c2) * 8 + hk * 4 + hm * 2 + lo;
}
__device__ __forceinline__ int off_B16(int n, int kk) {
    int ks = kk >> 4, kr = kk & 15;
    int hk = kr >> 3, c2 = (kr & 7) >> 1, lo = kr & 1;
    int ng = n >> 3, lh = n & 7;
    return (((ks * 32 + ng) * 32) + lh * 4 + c2) * 4 + hk * 2 + lo;
}

// ---------------------------------------------------------------------------
// Prepass: fp32 -> fp16 RNE + permute
// ---------------------------------------------------------------------------
// src [M][Ksrc] -> A-perm [128][32] tiles; grid (Ksrc/32, M/128)
__global__ void permuteA_kernel(const float* __restrict__ src, __half* __restrict__ dst, int Ksrc) {
    __shared__ __half sp[A_TILE_HALFS];
    int tid = threadIdx.x;
    const float* s0 = src + (size_t)blockIdx.y * 128 * Ksrc + blockIdx.x * 32;
#pragma unroll
    for (int i = 0; i < 16; i++) {
        int idx = tid + i * 256;
        int r = idx >> 5, kk = idx & 31;
        sp[off_A16(r, kk)] = __float2half_rn(s0[(size_t)r * Ksrc + kk]);
    }
    __syncthreads();
    uint4* d4 = (uint4*)(dst + ((size_t)blockIdx.y * gridDim.x + blockIdx.x) * A_TILE_HALFS);
#pragma unroll
    for (int i = 0; i < 2; i++) d4[tid + i * 256] = ((uint4*)sp)[tid + i * 256];
}

// src [Ktot][Nsrc] -> B-perm [256][32] tiles; grid (Ktot/32, Nsrc/256)
__global__ void permuteB_kernel(const float* __restrict__ src, __half* __restrict__ dst, int Nsrc) {
    __shared__ __half sp[B_TILE_HALFS];
    int tid = threadIdx.x;
    const float* s0 = src + (size_t)blockIdx.x * 32 * Nsrc + blockIdx.y * 256;
#pragma unroll
    for (int i = 0; i < 32; i++) {
        int idx = tid + i * 256;
        int kk = idx >> 8, nn = idx & 255;
        sp[off_B16(nn, kk)] = __float2half_rn(s0[(size_t)kk * Nsrc + nn]);
    }
    __syncthreads();
    uint4* d4 = (uint4*)(dst + ((size_t)blockIdx.y * gridDim.x + blockIdx.x) * B_TILE_HALFS);
#pragma unroll
    for (int i = 0; i < 4; i++) d4[tid + i * 256] = ((uint4*)sp)[tid + i * 256];
}

// ---------------------------------------------------------------------------
// fp16 GEMM, CTA 128x256xBK32, 512 threads (16 warps of 64x32), 1 CTA/SM
//   mode 0: dstH (fp16 A-perm tiles) = fp16(relu(acc + bias))   [H for GEMM2]
//   mode 1: dstf (fp32 row-major, width Nnat) = pad ? 0 : acc + bias
// ---------------------------------------------------------------------------
__global__ void __launch_bounds__(NTHREADS, 1)
gemm_f16_kernel(const __half* __restrict__ A, const __half* __restrict__ Bt,
                const float* __restrict__ bias, const int* __restrict__ padding,
                __half* __restrict__ dstH, float* __restrict__ dstf,
                int numChunks, int Nnat, int ldTiles, int mode) {
    extern __shared__ float smem[];
    const uint32_t smem_base = smem_u32(smem);
    const int tid = threadIdx.x, lane = tid & 31, wid = tid >> 5;
    const int warp_m = wid & 1;        // 2 warps along M (64 rows)
    const int warp_n = wid >> 1;       // 8 warps along N (32 cols)

    const __half* aTiles = A  + (size_t)blockIdx.y * numChunks * A_TILE_HALFS;
    const __half* bTiles = Bt + (size_t)blockIdx.x * numChunks * B_TILE_HALFS;
    const uint32_t bStage0 = smem_base + STAGES * A_TILE_BYTES;

    auto load_stage = [&](int chunk, int s) {
        const __half* aT = aTiles + (size_t)chunk * A_TILE_HALFS;
        const __half* bT = bTiles + (size_t)chunk * B_TILE_HALFS;
        uint32_t da = smem_base + s * A_TILE_BYTES;
        uint32_t db = bStage0 + s * B_TILE_BYTES;
        cp_async16(da + tid * 16, aT + tid * 8);      // 512 x 16B = 8 KB
#pragma unroll
        for (int t = 0; t < 2; t++) {
            int idx = tid + t * NTHREADS;
            cp_async16(db + idx * 16, bT + idx * 8);  // 1024 x 16B = 16 KB
        }
    };

    // prologue: STAGES-1 = 3 chunks committed
#pragma unroll
    for (int s = 0; s < STAGES - 1; s++) {
        load_stage(s, s);
        CP_COMMIT();
    }

    float acc[4][4][4];
#pragma unroll
    for (int mt = 0; mt < 4; mt++)
#pragma unroll
        for (int nt = 0; nt < 4; nt++)
#pragma unroll
            for (int j = 0; j < 4; j++) acc[mt][nt][j] = 0.f;

    const uint32_t laneA = lane * 16;
    const uint32_t laneB = lane * 8;

    uint32_t afr[2][4][4], bfr[2][4][2];
    auto load_frags = [&](int ks, int buf, uint32_t aBase, uint32_t bBase) {
#pragma unroll
        for (int mt = 0; mt < 4; mt++)
            lds128(afr[buf][mt], aBase + (uint32_t)((ks * 8 + warp_m * 4 + mt) * 32) * 16u);
#pragma unroll
        for (int nt = 0; nt < 4; nt++)
            lds64(bfr[buf][nt], bBase + (uint32_t)((ks * 32 + warp_n * 4 + nt) * 32) * 8u);
    };

    int buf = 0;
    for (int c = 0; c < numChunks; c++) {
        // wait(1): committed = c+3 groups -> chunks 0..c+1 resident
        CP_WAIT(STAGES - 3);
        __syncthreads();
        int next = c + STAGES - 1;
        if (next < numChunks) load_stage(next, next & (STAGES - 1));
        CP_COMMIT();

        const uint32_t aBase  = smem_base + (c & (STAGES - 1)) * A_TILE_BYTES + laneA;
        const uint32_t bBase  = bStage0 + (c & (STAGES - 1)) * B_TILE_BYTES + laneB;
        const uint32_t aBaseN = smem_base + ((c + 1) & (STAGES - 1)) * A_TILE_BYTES + laneA;
        const uint32_t bBaseN = bStage0 + ((c + 1) & (STAGES - 1)) * B_TILE_BYTES + laneB;

        if (c == 0) load_frags(0, buf, aBase, bBase);   // one-time prologue load

#pragma unroll
        for (int ks = 0; ks < 2; ks++) {
            const int nb = buf ^ 1;
            if (ks < 1)                    load_frags(ks + 1, nb, aBase, bBase);
            else if (c + 1 < numChunks)    load_frags(0, nb, aBaseN, bBaseN);  // cross-chunk
#pragma unroll
            for (int mt = 0; mt < 4; mt++)
#pragma unroll
                for (int nt = 0; nt < 4; nt++)
                    mma_f16(acc[mt][nt], afr[buf][mt], bfr[buf][nt]);
            buf = nb;
        }
        // next iteration's top barrier orders the stage overwrite (CUTLASS invariant)
    }
    __syncthreads();                     // protect epilogue smem staging

    if (mode == 0) {
        // Stage fp32 tile (128x256, stride 260), then emit fp16 A-perm tiles kt 0..7
        const int LDSN = 260;
        float* snat = smem;              // 128*260*4 = 133120 B
#pragma unroll
        for (int mt = 0; mt < 4; mt++) {
            int r0 = warp_m * 64 + mt * 16 + (lane >> 2);
#pragma unroll
            for (int hm = 0; hm < 2; hm++) {
                int r = r0 + hm * 8;
#pragma unroll
                for (int nt = 0; nt < 4; nt++) {
                    int col = warp_n * 32 + nt * 8 + (lane & 3) * 2;
                    float2 bv = *reinterpret_cast<const float2*>(bias + blockIdx.x * BN + col);
                    snat[r * LDSN + col]     = fmaxf(acc[mt][nt][hm * 2 + 0] + bv.x, 0.f);
                    snat[r * LDSN + col + 1] = fmaxf(acc[mt][nt][hm * 2 + 1] + bv.y, 0.f);
                }
            }
        }
        __syncthreads();
#pragma unroll
        for (int kt = 0; kt < 8; kt++) {
            uint4* dT = (uint4*)(dstH + ((size_t)blockIdx.y * ldTiles + blockIdx.x * 8 + kt) * A_TILE_HALFS);
            {
                int chunk = tid;                     // 512 chunks of 16B per tile
                int ln = chunk & 31, rest = chunk >> 5;
                int g = rest & 7, ks = rest >> 3;    // ks in {0,1}
                int r0 = g * 16 + (ln >> 2);
                int c0 = kt * 32 + ks * 16 + (ln & 3) * 2;
                __half2 p0 = __floats2half2_rn(snat[r0 * LDSN + c0],           snat[r0 * LDSN + c0 + 1]);
                __half2 p1 = __floats2half2_rn(snat[(r0 + 8) * LDSN + c0],     snat[(r0 + 8) * LDSN + c0 + 1]);
                __half2 p2 = __floats2half2_rn(snat[r0 * LDSN + c0 + 8],       snat[r0 * LDSN + c0 + 9]);
                __half2 p3 = __floats2half2_rn(snat[(r0 + 8) * LDSN + c0 + 8], snat[(r0 + 8) * LDSN + c0 + 9]);
                uint4 o;
                o.x = *reinterpret_cast<uint32_t*>(&p0);
                o.y = *reinterpret_cast<uint32_t*>(&p1);
                o.z = *reinterpret_cast<uint32_t*>(&p2);
                o.w = *reinterpret_cast<uint32_t*>(&p3);
                dT[chunk] = o;
            }
        }
    } else {
        const int m0 = blockIdx.y * BM, n0 = blockIdx.x * BN;
#pragma unroll
        for (int mt = 0; mt < 4; mt++) {
            int row0 = m0 + warp_m * 64 + mt * 16 + (lane >> 2);
#pragma unroll
            for (int hm = 0; hm < 2; hm++) {
                int row = row0 + hm * 8;
                int pad = padding[row];
                float* drow = dstf + (size_t)row * Nnat;
#pragma unroll
                for (int nt = 0; nt < 4; nt++) {
                    int col = n0 + warp_n * 32 + nt * 8 + (lane & 3) * 2;
                    float2 bv = *reinterpret_cast<const float2*>(bias + col);
                    float v0 = acc[mt][nt][hm * 2 + 0] + bv.x;
                    float v1 = acc[mt][nt][hm * 2 + 1] + bv.y;
                    if (pad != 0) { v0 = 0.f; v1 = 0.f; }
                    *reinterpret_cast<float2*>(drow + col) = make_float2(v0, v1);
                }
            }
        }
    }
}

// ---------------------------------------------------------------------------
// Host side
// ---------------------------------------------------------------------------
extern "C" void kernel_launch(void* const* d_in, const int* in_sizes, int n_in,
                              void* d_out, int out_size) {
    const float* x   = (const float*)d_in[0];
    const int*   pad = (const int*)  d_in[1];
    const float* W1  = (const float*)d_in[2];
    const float* b1  = (const float*)d_in[3];
    const float* W2  = (const float*)d_in[4];
    const float* b2  = (const float*)d_in[5];
    float*       out = (float*)d_out;

    void *pXr, *pW1T, *pW2T, *pH;
    cudaGetSymbolAddress(&pXr,  g_Xr);
    cudaGetSymbolAddress(&pW1T, g_W1T);
    cudaGetSymbolAddress(&pW2T, g_W2T);
    cudaGetSymbolAddress(&pH,   g_H);

    cudaFuncSetAttribute(gemm_f16_kernel,
                         cudaFuncAttributeMaxDynamicSharedMemorySize, SMEM_BYTES);

    // Prepass: fp32 -> fp16 RNE + permute
    permuteA_kernel<<<dim3(HD / 32, TT / 128), 256>>>(x,  (__half*)pXr,  HD);
    permuteB_kernel<<<dim3(HD / 32, FD / 256), 256>>>(W1, (__half*)pW1T, FD);
    permuteB_kernel<<<dim3(FD / 32, HD / 256), 256>>>(W2, (__half*)pW2T, HD);

    // GEMM1: H(fp16 A-perm) = fp16(relu(X @ W1 + b1));  grid 16 x 128
    gemm_f16_kernel<<<dim3(FD / BN, TT / BM), NTHREADS, SMEM_BYTES>>>(
        (const __half*)pXr, (const __half*)pW1T, b1, nullptr,
        (__half*)pH, nullptr, HD / 32, FD, FD / 32, 0);

    // GEMM2: out = mask(H @ W2 + b2);  grid 4 x 128
    gemm_f16_kernel<<<dim3(HD / BN, TT / BM), NTHREADS, SMEM_BYTES>>>(
        (const __half*)pH, (const __half*)pW2T, b2, pad,
        nullptr, out, FD / 32, HD, 0, 1);
}

// round 16
// speedup vs baseline: 1.1606x; 1.1606x over previous
#include <cuda_runtime.h>
#include <cuda_fp16.h>
#include <cstdint>

// ---------------------------------------------------------------------------
// Problem dims (fixed): B=4, L=4096, H=1024, F=4096
// ---------------------------------------------------------------------------
constexpr int TT = 16384;   // tokens
constexpr int HD = 1024;
constexpr int FD = 4096;

constexpr int BM = 128, BN = 128, BK = 64;
constexpr int STAGES = 3;
constexpr int TILE_HALFS  = BM * BK;           // 8192 fp16 per 128x64 tile
constexpr int TILE_BYTES  = TILE_HALFS * 2;    // 16 KB
constexpr int SMEM_BYTES  = STAGES * 2 * TILE_BYTES;  // 96 KB (epi 67.6KB fits)

// ---------------------------------------------------------------------------
// Scratch (allocation-free rule: module-scope device globals), fp16 permuted
// ---------------------------------------------------------------------------
__device__ __align__(1024) __half g_Xr [(size_t)TT * HD];   //  32 MB
__device__ __align__(1024) __half g_W1T[(size_t)FD * HD];   //   8 MB
__device__ __align__(1024) __half g_W2T[(size_t)HD * FD];   //   8 MB
__device__ __align__(1024) __half g_H  [(size_t)TT * FD];   // 134 MB

// ---------------------------------------------------------------------------
// Helpers
// ---------------------------------------------------------------------------
__device__ __forceinline__ uint32_t smem_u32(const void* p) {
    uint32_t a;
    asm("{ .reg .u64 t; cvta.to.shared.u64 t, %1; cvt.u32.u64 %0, t; }" : "=r"(a) : "l"(p));
    return a;
}

__device__ __forceinline__ void cp_async16(uint32_t smem_addr, const void* gptr) {
    asm volatile("cp.async.cg.shared.global [%0], [%1], 16;"
                 :: "r"(smem_addr), "l"(gptr) : "memory");
}
#define CP_COMMIT() asm volatile("cp.async.commit_group;" ::: "memory")
#define CP_WAIT(n)  asm volatile("cp.async.wait_group %0;" :: "n"(n) : "memory")

__device__ __forceinline__ void lds128(uint32_t* r, uint32_t addr) {
    asm volatile("ld.shared.v4.b32 {%0,%1,%2,%3}, [%4];"
                 : "=r"(r[0]), "=r"(r[1]), "=r"(r[2]), "=r"(r[3]) : "r"(addr));
}
__device__ __forceinline__ void lds64(uint32_t* r, uint32_t addr) {
    asm volatile("ld.shared.v2.b32 {%0,%1}, [%2];"
                 : "=r"(r[0]), "=r"(r[1]) : "r"(addr));
}

// fp16 MMA: D(f32) += A(f16) * B(f16), 16x8x16
__device__ __forceinline__ void mma_f16(float* c, const uint32_t* a, const uint32_t* b) {
    asm volatile(
        "mma.sync.aligned.m16n8k16.row.col.f32.f16.f16.f32 "
        "{%0,%1,%2,%3}, {%4,%5,%6,%7}, {%8,%9}, {%0,%1,%2,%3};"
        : "+f"(c[0]), "+f"(c[1]), "+f"(c[2]), "+f"(c[3])
        : "r"(a[0]), "r"(a[1]), "r"(a[2]), "r"(a[3]), "r"(b[0]), "r"(b[1]));
}

// ---------------------------------------------------------------------------
// fp16 fragment layouts within one [128 rows][64 k] tile (8192 halfs):
//   A: [ks:4][g:8][lane:32][8 fp16]  — thread's 4 A-regs = one 16B chunk
//   B: [ks:4][ng:16][lane:32][4 fp16] — thread's 2 B-regs = one 8B chunk
// ---------------------------------------------------------------------------
__device__ __forceinline__ int off_A16(int r, int kk) {
    int ks = kk >> 4, kr = kk & 15;
    int hk = kr >> 3, c2 = (kr & 7) >> 1, lo = kr & 1;
    int g = r >> 4, rr = r & 15, hm = rr >> 3, lh = rr & 7;
    return (((ks * 8 + g) * 32) + lh * 4 + c2) * 8 + hk * 4 + hm * 2 + lo;
}
__device__ __forceinline__ int off_B16(int n, int kk) {
    int ks = kk >> 4, kr = kk & 15;
    int hk = kr >> 3, c2 = (kr & 7) >> 1, lo = kr & 1;
    int ng = n >> 3, lh = n & 7;
    return (((ks * 16 + ng) * 32) + lh * 4 + c2) * 4 + hk * 2 + lo;
}

// ---------------------------------------------------------------------------
// Prepass: fp32 -> fp16 RNE + permute into [128][64] tiles
// ---------------------------------------------------------------------------
// src [M][Ksrc] row-major -> A-perm tiles; grid (Ksrc/64, M/128)
__global__ void permuteA_kernel(const float* __restrict__ src, __half* __restrict__ dst, int Ksrc) {
    __shared__ __half sp[TILE_HALFS];
    int tid = threadIdx.x;
    const float* s0 = src + (size_t)blockIdx.y * 128 * Ksrc + blockIdx.x * 64;
#pragma unroll
    for (int i = 0; i < 32; i++) {
        int idx = tid + i * 256;
        int r = idx >> 6, kk = idx & 63;
        sp[off_A16(r, kk)] = __float2half_rn(s0[(size_t)r * Ksrc + kk]);
    }
    __syncthreads();
    uint4* d4 = (uint4*)(dst + ((size_t)blockIdx.y * gridDim.x + blockIdx.x) * TILE_HALFS);
#pragma unroll
    for (int i = 0; i < 4; i++) d4[tid + i * 256] = ((uint4*)sp)[tid + i * 256];
}

// src [Ktot][Nsrc] row-major -> B-perm tiles over [128 n][64 k]; grid (Ktot/64, Nsrc/128)
__global__ void permuteB_kernel(const float* __restrict__ src, __half* __restrict__ dst, int Nsrc) {
    __shared__ __half sp[TILE_HALFS];
    int tid = threadIdx.x;
    const float* s0 = src + (size_t)blockIdx.x * 64 * Nsrc + blockIdx.y * 128;
#pragma unroll
    for (int i = 0; i < 32; i++) {
        int idx = tid + i * 256;
        int kk = idx >> 7, nn = idx & 127;
        sp[off_B16(nn, kk)] = __float2half_rn(s0[(size_t)kk * Nsrc + nn]);
    }
    __syncthreads();
    uint4* d4 = (uint4*)(dst + ((size_t)blockIdx.y * gridDim.x + blockIdx.x) * TILE_HALFS);
#pragma unroll
    for (int i = 0; i < 4; i++) d4[tid + i * 256] = ((uint4*)sp)[tid + i * 256];
}

// ---------------------------------------------------------------------------
// fp16 GEMM, CTA 128x128xBK64, 3-stage wait(0), cross-chunk frag prefetch,
// 8 warps of 64x32, 2 CTAs/SM
//   mode 0: dstH (fp16 A-perm [128][64] tiles) = fp16(relu(acc+bias))  [H]
//   mode 1: dstf (fp32 row-major, width Nnat) = pad ? 0 : acc + bias
// ---------------------------------------------------------------------------
__global__ void __launch_bounds__(256, 2)
gemm_f16_kernel(const __half* __restrict__ A, const __half* __restrict__ Bt,
                const float* __restrict__ bias, const int* __restrict__ padding,
                __half* __restrict__ dstH, float* __restrict__ dstf,
                int numChunks, int Nnat, int ldTiles, int mode) {
    extern __shared__ float smem[];
    const uint32_t smem_base = smem_u32(smem);
    const int tid = threadIdx.x, lane = tid & 31, wid = tid >> 5;
    const int warp_m = wid & 1;        // 2 warps along M
    const int warp_n = wid >> 1;       // 4 warps along N

    const __half* aTiles = A  + (size_t)blockIdx.y * numChunks * TILE_HALFS;
    const __half* bTiles = Bt + (size_t)blockIdx.x * numChunks * TILE_HALFS;

    auto load_stage = [&](int chunk, int s) {
        const __half* aT = aTiles + (size_t)chunk * TILE_HALFS;
        const __half* bT = bTiles + (size_t)chunk * TILE_HALFS;
        uint32_t da = smem_base + s * TILE_BYTES;
        uint32_t db = smem_base + (STAGES + s) * TILE_BYTES;
#pragma unroll
        for (int t = 0; t < 4; t++) {
            int idx = tid + t * 256;
            cp_async16(da + idx * 16, aT + idx * 8);
        }
#pragma unroll
        for (int t = 0; t < 4; t++) {
            int idx = tid + t * 256;
            cp_async16(db + idx * 16, bT + idx * 8);
        }
    };

    // prologue: chunks 0,1 committed
#pragma unroll
    for (int s = 0; s < STAGES - 1; s++) {
        load_stage(s, s);
        CP_COMMIT();
    }

    float acc[4][4][4];
#pragma unroll
    for (int mt = 0; mt < 4; mt++)
#pragma unroll
        for (int nt = 0; nt < 4; nt++)
#pragma unroll
            for (int j = 0; j < 4; j++) acc[mt][nt][j] = 0.f;

    const uint32_t laneA = lane * 16;
    const uint32_t laneB = lane * 8;

    uint32_t afr[2][4][4], bfr[2][4][2];
    auto load_frags = [&](int ks, int buf, uint32_t aBase, uint32_t bBase) {
#pragma unroll
        for (int mt = 0; mt < 4; mt++)
            lds128(afr[buf][mt], aBase + (uint32_t)((ks * 8 + warp_m * 4 + mt) * 32) * 16u);
#pragma unroll
        for (int nt = 0; nt < 4; nt++)
            lds64(bfr[buf][nt], bBase + (uint32_t)((ks * 16 + warp_n * 4 + nt) * 32) * 8u);
    };

    int buf = 0;
    int sc = 0, scN = 1;                 // stage of chunk c, chunk c+1
    for (int c = 0; c < numChunks; c++) {
        // wait(0): all committed groups (chunks <= c+1) complete
        CP_WAIT(0);
        __syncthreads();
        // commit chunk c+2 AFTER the barrier: its stage (c+2)%3 == (c-1)%3 was
        // last read in iter c-1, and all warps past the barrier finished it.
        int next = c + STAGES - 1;
        if (next < numChunks) {
            int sn = next - STAGES * (next / STAGES);   // next % 3
            load_stage(next, sn);
        }
        CP_COMMIT();

        const uint32_t aBase  = smem_base + sc * TILE_BYTES + laneA;
        const uint32_t bBase  = smem_base + (STAGES + sc) * TILE_BYTES + laneB;
        const uint32_t aBaseN = smem_base + scN * TILE_BYTES + laneA;
        const uint32_t bBaseN = smem_base + (STAGES + scN) * TILE_BYTES + laneB;

        if (c == 0) load_frags(0, buf, aBase, bBase);   // one-time prologue load

#pragma unroll
        for (int ks = 0; ks < 4; ks++) {
            const int nb = buf ^ 1;
            if (ks < 3)                    load_frags(ks + 1, nb, aBase, bBase);
            else if (c + 1 < numChunks)    load_frags(0, nb, aBaseN, bBaseN);  // cross-chunk
#pragma unroll
            for (int mt = 0; mt < 4; mt++)
#pragma unroll
                for (int nt = 0; nt < 4; nt++)
                    mma_f16(acc[mt][nt], afr[buf][mt], bfr[buf][nt]);
            buf = nb;
        }
        sc = scN; scN = scN + 1 == STAGES ? 0 : scN + 1;
    }
    __syncthreads();                     // protect epilogue smem staging

    if (mode == 0) {
        // Stage fp32 tile (128x128, stride 132), then emit fp16 A-perm [128][64] tiles
        const int LDSN = 132;
        float* snat = smem;              // 128*132*4 = 67584 B <= 96 KB
#pragma unroll
        for (int mt = 0; mt < 4; mt++) {
            int r0 = warp_m * 64 + mt * 16 + (lane >> 2);
#pragma unroll
            for (int hm = 0; hm < 2; hm++) {
                int r = r0 + hm * 8;
#pragma unroll
                for (int nt = 0; nt < 4; nt++) {
                    int col = warp_n * 32 + nt * 8 + (lane & 3) * 2;
                    float2 bv = *reinterpret_cast<const float2*>(bias + blockIdx.x * BN + col);
                    snat[r * LDSN + col]     = fmaxf(acc[mt][nt][hm * 2 + 0] + bv.x, 0.f);
                    snat[r * LDSN + col + 1] = fmaxf(acc[mt][nt][hm * 2 + 1] + bv.y, 0.f);
                }
            }
        }
        __syncthreads();
#pragma unroll
        for (int kt = 0; kt < 2; kt++) {
            uint4* dT = (uint4*)(dstH + ((size_t)blockIdx.y * ldTiles + blockIdx.x * 2 + kt) * TILE_HALFS);
#pragma unroll
            for (int i = 0; i < 4; i++) {
                int chunk = tid + i * 256;           // 1024 chunks of 16B per tile
                int ln = chunk & 31, rest = chunk >> 5;
                int g = rest & 7, ks = rest >> 3;    // ks in {0..3}
                int r0 = g * 16 + (ln >> 2);
                int c0 = kt * 64 + ks * 16 + (ln & 3) * 2;
                __half2 p0 = __floats2half2_rn(snat[r0 * LDSN + c0],           snat[r0 * LDSN + c0 + 1]);
                __half2 p1 = __floats2half2_rn(snat[(r0 + 8) * LDSN + c0],     snat[(r0 + 8) * LDSN + c0 + 1]);
                __half2 p2 = __floats2half2_rn(snat[r0 * LDSN + c0 + 8],       snat[r0 * LDSN + c0 + 9]);
                __half2 p3 = __floats2half2_rn(snat[(r0 + 8) * LDSN + c0 + 8], snat[(r0 + 8) * LDSN + c0 + 9]);
                uint4 o;
                o.x = *reinterpret_cast<uint32_t*>(&p0);
                o.y = *reinterpret_cast<uint32_t*>(&p1);
                o.z = *reinterpret_cast<uint32_t*>(&p2);
                o.w = *reinterpret_cast<uint32_t*>(&p3);
                dT[chunk] = o;
            }
        }
    } else {
        const int m0 = blockIdx.y * BM, n0 = blockIdx.x * BN;
#pragma unroll
        for (int mt = 0; mt < 4; mt++) {
            int row0 = m0 + warp_m * 64 + mt * 16 + (lane >> 2);
#pragma unroll
            for (int hm = 0; hm < 2; hm++) {
                int row = row0 + hm * 8;
                int pad = padding[row];
                float* drow = dstf + (size_t)row * Nnat;
#pragma unroll
                for (int nt = 0; nt < 4; nt++) {
                    int col = n0 + warp_n * 32 + nt * 8 + (lane & 3) * 2;
                    float2 bv = *reinterpret_cast<const float2*>(bias + col);
                    float v0 = acc[mt][nt][hm * 2 + 0] + bv.x;
                    float v1 = acc[mt][nt][hm * 2 + 1] + bv.y;
                    if (pad != 0) { v0 = 0.f; v1 = 0.f; }
                    *reinterpret_cast<float2*>(drow + col) = make_float2(v0, v1);
                }
            }
        }
    }
}

// ---------------------------------------------------------------------------
// Host side
// ---------------------------------------------------------------------------
extern "C" void kernel_launch(void* const* d_in, const int* in_sizes, int n_in,
                              void* d_out, int out_size) {
    const float* x   = (const float*)d_in[0];
    const int*   pad = (const int*)  d_in[1];
    const float* W1  = (const float*)d_in[2];
    const float* b1  = (const float*)d_in[3];
    const float* W2  = (const float*)d_in[4];
    const float* b2  = (const float*)d_in[5];
    float*       out = (float*)d_out;

    void *pXr, *pW1T, *pW2T, *pH;
    cudaGetSymbolAddress(&pXr,  g_Xr);
    cudaGetSymbolAddress(&pW1T, g_W1T);
    cudaGetSymbolAddress(&pW2T, g_W2T);
    cudaGetSymbolAddress(&pH,   g_H);

    cudaFuncSetAttribute(gemm_f16_kernel,
                         cudaFuncAttributeMaxDynamicSharedMemorySize, SMEM_BYTES);

    // Prepass: fp32 -> fp16 RNE + permute ([128][64] tiles)
    permuteA_kernel<<<dim3(HD / 64, TT / 128), 256>>>(x,  (__half*)pXr,  HD);
    permuteB_kernel<<<dim3(HD / 64, FD / 128), 256>>>(W1, (__half*)pW1T, FD);
    permuteB_kernel<<<dim3(FD / 64, HD / 128), 256>>>(W2, (__half*)pW2T, HD);

    // GEMM1: H(fp16 A-perm) = fp16(relu(X @ W1 + b1));  grid 32 x 128
    gemm_f16_kernel<<<dim3(FD / BN, TT / BM), 256, SMEM_BYTES>>>(
        (const __half*)pXr, (const __half*)pW1T, b1, nullptr,
        (__half*)pH, nullptr, HD / 64, FD, FD / 64, 0);

    // GEMM2: out = mask(H @ W2 + b2);  grid 8 x 128
    gemm_f16_kernel<<<dim3(HD / BN, TT / BM), 256, SMEM_BYTES>>>(
        (const __half*)pH, (const __half*)pW2T, b2, pad,
        nullptr, out, FD / 64, HD, 0, 1);
}